// round 15
// baseline (speedup 1.0000x reference)
#include <cuda_runtime.h>
#include <cuda_fp16.h>
#include <cstdint>

#define SEQ   256
#define BATCH 4
#define DIM   512
#define NKV   32768
#define RQ    (SEQ * BATCH)          // 1024
#define ASPLIT 32
#define AKSLICE (NKV / ASPLIT)       // 1024
#define NSUM  (NKV / 128)            // 256

typedef unsigned int u32;
typedef __half fp16;

// ======================= device scratch ====================================
__device__ __align__(16) fp16 g_dkh[NKV * DIM];            // dk fp16 [NKV,DIM]
__device__ __align__(16) fp16 g_dvh[NKV * DIM];            // dv fp16 [NKV,DIM]
__device__ __align__(16) fp16 g_qbh[RQ * DIM];
__device__ __align__(16) fp16 g_q2 [RQ * DIM];
__device__ __align__(16) fp16 g_wqt[DIM * DIM];            // Wq^T
__device__ __align__(16) fp16 g_wkt[DIM * DIM];            // Wk^T
__device__ __align__(16) fp16 g_wkq[DIM * DIM];            // alpha*Wk^T*Wq
__device__ __align__(16) fp16 g_wvh[DIM * DIM];
__device__ __align__(16) fp16 g_g1h[DIM * 2 * DIM];
__device__ __align__(16) float g_bias2[DIM];
__device__ __align__(16) fp16 g_wb[(size_t)RQ * NKV];      // exp weights fp16
__device__ __align__(16) float g_sumpart[(size_t)RQ * NSUM];
__device__ __align__(16) fp16 g_attnp[RQ * DIM];
__device__ __align__(16) fp16 g_cath[RQ * 2 * DIM];
__device__ __align__(16) float g_attn[RQ * DIM];
__device__ __align__(16) float g_part[(size_t)ASPLIT * RQ * DIM];   // split-K scratch

// ======================= PTX helpers =======================================
__device__ __forceinline__ u32 smem_u32(const void* p) {
    u32 a;
    asm("{ .reg .u64 t; cvta.to.shared.u64 t, %1; cvt.u32.u64 %0, t; }"
        : "=r"(a) : "l"(p));
    return a;
}

#define CP_ASYNC16(dst, src) \
    asm volatile("cp.async.cg.shared.global [%0], [%1], 16;" :: "r"(dst), "l"(src))
#define CP_COMMIT() asm volatile("cp.async.commit_group;" ::: "memory")
#define CP_WAIT(n)  asm volatile("cp.async.wait_group %0;" :: "n"(n) : "memory")

#define LDMX4(r, addr) \
    asm volatile("ldmatrix.sync.aligned.m8n8.x4.shared.b16 {%0,%1,%2,%3}, [%4];" \
        : "=r"((r)[0]), "=r"((r)[1]), "=r"((r)[2]), "=r"((r)[3]) : "r"(addr))

#define LDMX4T(r, addr) \
    asm volatile("ldmatrix.sync.aligned.m8n8.x4.trans.shared.b16 {%0,%1,%2,%3}, [%4];" \
        : "=r"((r)[0]), "=r"((r)[1]), "=r"((r)[2]), "=r"((r)[3]) : "r"(addr))

#define MMA_F16(d, a, b) \
    asm volatile("mma.sync.aligned.m16n8k16.row.col.f32.f16.f16.f32 " \
        "{%0,%1,%2,%3}, {%4,%5,%6,%7}, {%8,%9}, {%0,%1,%2,%3};" \
        : "+f"((d)[0]), "+f"((d)[1]), "+f"((d)[2]), "+f"((d)[3]) \
        : "r"((a)[0]), "r"((a)[1]), "r"((a)[2]), "r"((a)[3]), \
          "r"((b)[0]), "r"((b)[1]))

__device__ __forceinline__ float fast_exp(float x) {
    float t = x * 1.4426950408889634f;
    t = fmaxf(t, -125.0f);
    float fi = floorf(t);
    float f = t - fi;
    float p = 1.5403530393381608e-4f;
    p = fmaf(p, f, 1.3333558146428443e-3f);
    p = fmaf(p, f, 9.618129107628477e-3f);
    p = fmaf(p, f, 5.550410866482158e-2f);
    p = fmaf(p, f, 2.402265069591007e-1f);
    p = fmaf(p, f, 6.931471805599453e-1f);
    p = fmaf(p, f, 1.0f);
    return p * __int_as_float(((int)fi + 127) << 23);
}

// ======================= pipelined HMMA fp16 GEMM ==========================
// C[M,N] = A[M,K] * B^T, fp32 accumulate
// BKN=0: B stored [N,K] row-major; BKN=1: B stored [K,N] row-major
// out_mode: 0 fp32 partials (z*strideZ, alpha+bias applied);
//           1 fp16; 3 exp(acc)->fp16 + per-(row,ntile) partial sums;
//           4 dual write: fp32 Cf (ld=ldc) AND fp16 Ch (ld=strideZ)
#define GKC 64
#define SROW 144
#define TILE_B (128 * SROW)        // A tile bytes: 18432
#define GSMEM (3 * (2 * TILE_B))   // 110592

template<int BKN>
__global__ __launch_bounds__(256, 2)
void gemm_f16(const fp16* __restrict__ A, const fp16* __restrict__ B,
              float* __restrict__ Cf, fp16* __restrict__ Ch,
              int lda, int ldb, int ldc, int kslice,
              const float* __restrict__ bias, int bias_mode,
              float alpha, int swap, int out_mode,
              long long strideZ, float* __restrict__ sums)
{
    constexpr int SROWB = BKN ? 272 : SROW;
    constexpr int BT    = BKN ? 64 * 272 : TILE_B;
    constexpr int STG   = TILE_B + BT;

    extern __shared__ char smem[];
    const u32 sb = smem_u32(smem);
    const int tid = threadIdx.x;
    const int lane = tid & 31, wid = tid >> 5;
    const int wm = wid >> 1, wn = wid & 1;
    const int mtile = swap ? blockIdx.x : blockIdx.y;
    const int ntile = swap ? blockIdx.y : blockIdx.x;
    const int z = blockIdx.z;
    const long long kbase = (long long)z * kslice;
    const int NC = kslice / GKC;

    auto load_stage = [&](int c) {
        const u32 st = sb + (u32)(c % 3) * STG;
        const long long kb = kbase + (long long)c * GKC;
#pragma unroll
        for (int i = 0; i < 4; i++) {               // A tile: 128 rows x 128B
            const int idx = tid + i * 256;
            const int row = idx >> 3, ch = idx & 7;
            const u32 so = (u32)(row * SROW + ch * 16);
            const long long aoff = (long long)(mtile * 128 + row) * lda + kb + ch * 8;
            CP_ASYNC16(st + so, (const char*)(A + aoff));
        }
        if (BKN) {
#pragma unroll
            for (int i = 0; i < 4; i++) {           // B tile: 64 K-rows x 256B
                const int idx = tid + i * 256;
                const int row = idx >> 4, ch = idx & 15;
                const u32 so = (u32)(row * SROWB + ch * 16);
                const long long boff = (kb + row) * (long long)ldb
                                     + (long long)ntile * 128 + ch * 8;
                CP_ASYNC16(st + TILE_B + so, (const char*)(B + boff));
            }
        } else {
#pragma unroll
            for (int i = 0; i < 4; i++) {           // B tile: 128 N-rows x 128B
                const int idx = tid + i * 256;
                const int row = idx >> 3, ch = idx & 7;
                const u32 so = (u32)(row * SROWB + ch * 16);
                const long long boff = (long long)(ntile * 128 + row) * ldb + kb + ch * 8;
                CP_ASYNC16(st + TILE_B + so, (const char*)(B + boff));
            }
        }
        CP_COMMIT();
    };

    float acc[2][8][4];
#pragma unroll
    for (int mt = 0; mt < 2; mt++)
#pragma unroll
        for (int nt = 0; nt < 8; nt++)
#pragma unroll
            for (int j = 0; j < 4; j++) acc[mt][nt][j] = 0.f;

    load_stage(0);
    if (NC > 1) load_stage(1);

    const u32 a_row = (u32)(wm * 32 + (lane & 15));
    const u32 a_ke  = (u32)((lane >> 4) * 8);
    const u32 b_row = (u32)(wn * 64 + ((lane >> 4) << 3) + (lane & 7));
    const u32 b_ke  = (u32)(((lane >> 3) & 1) * 8);
    const u32 bt_k  = (u32)(((lane >> 3) & 1) * 8 + (lane & 7));
    const u32 bt_n  = (u32)((lane >> 4) << 3);

    for (int c = 0; c < NC; c++) {
        if (c + 1 < NC) { CP_WAIT(1); } else { CP_WAIT(0); }
        __syncthreads();
        if (c + 2 < NC) load_stage(c + 2);

        const u32 st = sb + (u32)(c % 3) * STG;
#pragma unroll
        for (int ks = 0; ks < 4; ks++) {
            const u32 k0 = ks * 16;
            u32 af[2][4], bfr[8][2];
#pragma unroll
            for (int mt = 0; mt < 2; mt++) {
                const u32 addr = st + (a_row + mt * 16) * SROW + (k0 + a_ke) * 2;
                LDMX4(af[mt], addr);
            }
#pragma unroll
            for (int nt2 = 0; nt2 < 4; nt2++) {
                u32 r[4];
                if (BKN) {
                    const u32 addr = st + TILE_B + (k0 + bt_k) * SROWB
                                   + (u32)(wn * 64 + nt2 * 16 + bt_n) * 2;
                    LDMX4T(r, addr);
                } else {
                    const u32 addr = st + TILE_B + (b_row + nt2 * 16) * SROWB
                                   + (k0 + b_ke) * 2;
                    LDMX4(r, addr);
                }
                bfr[2 * nt2][0] = r[0]; bfr[2 * nt2][1] = r[1];
                bfr[2 * nt2 + 1][0] = r[2]; bfr[2 * nt2 + 1][1] = r[3];
            }
#pragma unroll
            for (int mt = 0; mt < 2; mt++)
#pragma unroll
                for (int nt = 0; nt < 8; nt++)
                    MMA_F16(acc[mt][nt], af[mt], bfr[nt]);
        }
    }
    __syncthreads();

    // ---------------- epilogue ---------------------------------------------
    float* stage = (float*)smem;                    // [128][132]
    const int l4 = lane >> 2, l2 = (lane & 3) * 2;

#pragma unroll
    for (int mt = 0; mt < 2; mt++) {
        const int lr = wm * 32 + mt * 16 + l4;
#pragma unroll
        for (int nt = 0; nt < 8; nt++) {
            const int lc = wn * 64 + nt * 8 + l2;
            float v0, v1, v2, v3;
            if (out_mode == 3) {
                v0 = fast_exp(acc[mt][nt][0]);
                v1 = fast_exp(acc[mt][nt][1]);
                v2 = fast_exp(acc[mt][nt][2]);
                v3 = fast_exp(acc[mt][nt][3]);
            } else {
                float bc0 = 0.f, bc1 = 0.f;
                if (bias_mode == 1) {
                    bc0 = bias[ntile * 128 + lc];
                    bc1 = bias[ntile * 128 + lc + 1];
                }
                v0 = (acc[mt][nt][0] + bc0) * alpha;
                v1 = (acc[mt][nt][1] + bc1) * alpha;
                v2 = (acc[mt][nt][2] + bc0) * alpha;
                v3 = (acc[mt][nt][3] + bc1) * alpha;
            }
            stage[lr * 132 + lc] = v0;
            stage[lr * 132 + lc + 1] = v1;
            stage[(lr + 8) * 132 + lc] = v2;
            stage[(lr + 8) * 132 + lc + 1] = v3;
        }
    }
    __syncthreads();

    if (out_mode == 0) {
        float* Cp = Cf + (long long)z * strideZ
                  + (long long)(mtile * 128) * ldc + ntile * 128;
#pragma unroll
        for (int i = 0; i < 16; i++) {
            const int idx = tid + i * 256;
            const int rr = idx >> 5, c4 = (idx & 31) * 4;
            float4 v = *(float4*)&stage[rr * 132 + c4];
            *(float4*)(Cp + (long long)rr * ldc + c4) = v;
        }
    } else if (out_mode == 4) {
        const int ld2 = (int)strideZ;
        float* Cp = Cf + (long long)(mtile * 128) * ldc + ntile * 128;
        fp16* Hp = Ch + (long long)(mtile * 128) * ld2 + ntile * 128;
#pragma unroll
        for (int i = 0; i < 16; i++) {
            const int idx = tid + i * 256;
            const int rr = idx >> 5, c4 = (idx & 31) * 4;
            float4 v = *(float4*)&stage[rr * 132 + c4];
            *(float4*)(Cp + (long long)rr * ldc + c4) = v;
            __half2* hq = (__half2*)(Hp + (long long)rr * ld2 + c4);
            hq[0] = __floats2half2_rn(v.x, v.y);
            hq[1] = __floats2half2_rn(v.z, v.w);
        }
    } else {
        fp16* Hp = Ch + (long long)(mtile * 128) * ldc + ntile * 128;
#pragma unroll
        for (int i = 0; i < 16; i++) {
            const int idx = tid + i * 256;
            const int rr = idx >> 5, c4 = (idx & 31) * 4;
            float4 v = *(float4*)&stage[rr * 132 + c4];
            __half2* hq = (__half2*)(Hp + (long long)rr * ldc + c4);
            hq[0] = __floats2half2_rn(v.x, v.y);
            hq[1] = __floats2half2_rn(v.z, v.w);
        }
        if (out_mode == 3) {
            const int r = tid >> 1, h = tid & 1;
            float s = 0.f;
            const float* rp = &stage[r * 132 + h * 64];
#pragma unroll
            for (int j = 0; j < 64; j++) s += rp[j];
            s += __shfl_xor_sync(0xffffffffu, s, 1);
            if (h == 0)
                sums[(size_t)(mtile * 128 + r) * NSUM + ntile] = s;
        }
    }
}

// ======================= merged prep kernel ================================
#define NB_CVT 2048
#define NB_TT  512
#define NB_PREP 2048
#define NB_PALL (NB_CVT + NB_TT + NB_PREP)

__global__ void prep_all(const float4* __restrict__ dk, __half2* __restrict__ dkh,
                         const float4* __restrict__ dv, __half2* __restrict__ dvh,
                         const float4* __restrict__ wv, __half2* __restrict__ wvh,
                         const float4* __restrict__ wg1, __half2* __restrict__ g1h,
                         const float* __restrict__ wq, fp16* __restrict__ wqt,
                         const float* __restrict__ wk, fp16* __restrict__ wkt,
                         const float* __restrict__ q, const float* __restrict__ prev,
                         fp16* __restrict__ qbh, fp16* __restrict__ cath)
{
    __shared__ float tile[32][33];
    const int b = blockIdx.x;
    const int tid = threadIdx.x;

    if (b < NB_CVT) {
        const int N_DK = NKV * DIM / 4;
        const int N_WV = DIM * DIM / 4;
        const int N_G1 = DIM * 2 * DIM / 4;
        const int stride = NB_CVT * 256;
        const int t0 = b * 256 + tid;
        for (int i = t0; i < N_DK; i += stride) {
            float4 v = dk[i];
            dkh[2 * i]     = __floats2half2_rn(v.x, v.y);
            dkh[2 * i + 1] = __floats2half2_rn(v.z, v.w);
            float4 w = dv[i];
            dvh[2 * i]     = __floats2half2_rn(w.x, w.y);
            dvh[2 * i + 1] = __floats2half2_rn(w.z, w.w);
        }
        for (int i = t0; i < N_G1; i += stride) {
            float4 v = wg1[i];
            g1h[2 * i]     = __floats2half2_rn(v.x, v.y);
            g1h[2 * i + 1] = __floats2half2_rn(v.z, v.w);
            if (i < N_WV) {
                float4 w = wv[i];
                wvh[2 * i]     = __floats2half2_rn(w.x, w.y);
                wvh[2 * i + 1] = __floats2half2_rn(w.z, w.w);
            }
        }
    } else if (b < NB_CVT + NB_TT) {
        const int bb = b - NB_CVT;
        const int bx = bb & 15, by = (bb >> 4) & 15, bz = bb >> 8;
        const float* src = bz ? wk : wq;
        fp16* dst = bz ? wkt : wqt;
        const int c0 = bx * 32, r0 = by * 32;
        const int tx = tid & 31, ty = tid >> 5;     // 32 x 8
#pragma unroll
        for (int i = 0; i < 32; i += 8)
            tile[ty + i][tx] = src[(size_t)(r0 + ty + i) * DIM + c0 + tx];
        __syncthreads();
#pragma unroll
        for (int i = 0; i < 32; i += 8)
            dst[(size_t)(c0 + ty + i) * DIM + r0 + tx] = __float2half(tile[tx][ty + i]);
    } else {
        const int i = (b - NB_CVT - NB_TT) * 256 + tid;
        const int d = i & (DIM - 1);
        const int t = i >> 9;
        const int ba = t & (BATCH - 1);
        const int s = t >> 2;
        const int r = ba * SEQ + s;
        qbh[(size_t)r * DIM + d] = __float2half(q[i]);
        cath[(size_t)r * 2 * DIM + DIM + d] = __float2half(prev[i]);
    }
}

// bias2[j] = alpha * sum_k bq[k] * wkt[j,k]
__global__ void bias2_kernel(const float* __restrict__ bq, const fp16* __restrict__ wkt,
                             float* __restrict__ bias2, float alpha)
{
    const int j = blockIdx.x;                   // 0..511
    const int tid = threadIdx.x;                // 256
    const __half2 w = ((const __half2*)(wkt + (size_t)j * DIM))[tid];
    float s = fmaf(bq[2 * tid], __half2float(__low2half(w)),
                   bq[2 * tid + 1] * __half2float(__high2half(w)));
#pragma unroll
    for (int o = 16; o; o >>= 1) s += __shfl_xor_sync(0xffffffffu, s, o);
    __shared__ float red[8];
    if ((tid & 31) == 0) red[tid >> 5] = s;
    __syncthreads();
    if (tid == 0) {
        float ss = 0.f;
#pragma unroll
        for (int w8 = 0; w8 < 8; w8++) ss += red[w8];
        bias2[j] = ss * alpha;
    }
}

// fused: per-row invsum + 32-way split-K reduce + normalize -> attnp
__global__ void attn_reduce(const float* __restrict__ part, const float* __restrict__ sp,
                            fp16* __restrict__ attnp)
{
    const int r = blockIdx.x;                   // 0..RQ-1
    const int tid = threadIdx.x;                // 256 (== NSUM)
    __shared__ float red[8];
    __shared__ float invs;

    float s = sp[(size_t)r * NSUM + tid];
#pragma unroll
    for (int o = 16; o; o >>= 1) s += __shfl_xor_sync(0xffffffffu, s, o);
    if ((tid & 31) == 0) red[tid >> 5] = s;
    __syncthreads();
    if (tid == 0) {
        float ss = 0.f;
#pragma unroll
        for (int w = 0; w < 8; w++) ss += red[w];
        invs = 1.0f / ss;
    }
    __syncthreads();
    const float inv = invs;

#pragma unroll
    for (int h = 0; h < 2; h++) {
        const int d = h * 256 + tid;
        const size_t i = (size_t)r * DIM + d;
        float v = 0.f;
#pragma unroll
        for (int z = 0; z < ASPLIT; z++) v += part[(size_t)z * RQ * DIM + i];
        attnp[i] = __float2half(v * inv);
    }
}

// gate: read single fp32 slice + bg1 + relu + sigma + blend
__global__ void gate_sigma_final(const float* __restrict__ gg, const float* __restrict__ bg1,
                                 const float* __restrict__ Wg2, const float* __restrict__ bg2,
                                 const float* __restrict__ attn, const float* __restrict__ prev,
                                 float* __restrict__ out)
{
    const int r = blockIdx.x;
    const int tid = threadIdx.x;                // 128
    float s = 0.f;
    for (int d = tid; d < DIM; d += 128) {
        float v = fmaxf(gg[(size_t)r * DIM + d] + bg1[d], 0.f);
        s = fmaf(v, Wg2[d], s);
    }
#pragma unroll
    for (int o = 16; o; o >>= 1) s += __shfl_xor_sync(0xffffffffu, s, o);
    __shared__ float red[4];
    __shared__ float gsh;
    if ((tid & 31) == 0) red[tid >> 5] = s;
    __syncthreads();
    if (tid == 0) {
        float t = red[0] + red[1] + red[2] + red[3] + bg2[0];
        gsh = 1.0f / (1.0f + __expf(-t));
    }
    __syncthreads();
    const float g = gsh;
    const int b = r / SEQ, sq = r % SEQ;
    for (int d = tid; d < DIM; d += 128) {
        const int oi = (sq * BATCH + b) * DIM + d;
        float a = attn[(size_t)r * DIM + d];
        float p = prev[oi];
        out[oi] = fmaf(a - p, g, p);
    }
}

// ======================= launch =============================================
extern "C" void kernel_launch(void* const* d_in, const int* in_sizes, int n_in,
                              void* d_out, int out_size)
{
    (void)in_sizes; (void)n_in; (void)out_size;
    const float* q    = (const float*)d_in[0];
    const float* prev = (const float*)d_in[1];
    const float* Wq   = (const float*)d_in[2];
    const float* bq   = (const float*)d_in[3];
    const float* Wk   = (const float*)d_in[4];
    const float* bk   = (const float*)d_in[5];   (void)bk;  // cancels in softmax
    const float* Wv   = (const float*)d_in[6];
    const float* bv   = (const float*)d_in[7];
    const float* Wg1  = (const float*)d_in[8];
    const float* bg1  = (const float*)d_in[9];
    const float* Wg2  = (const float*)d_in[10];
    const float* bg2  = (const float*)d_in[11];
    const float* dk   = (const float*)d_in[12];
    const float* dv   = (const float*)d_in[13];
    float* out = (float*)d_out;

    cudaFuncSetAttribute(gemm_f16<0>, cudaFuncAttributeMaxDynamicSharedMemorySize, GSMEM);
    cudaFuncSetAttribute(gemm_f16<1>, cudaFuncAttributeMaxDynamicSharedMemorySize, GSMEM);

    fp16 *dkh, *dvh, *qbh, *q2, *wqt, *wkt, *wkq, *wvh, *g1h, *wb, *attnp, *cath;
    float *attn, *part, *sp, *bias2;
    cudaGetSymbolAddress((void**)&dkh, g_dkh);
    cudaGetSymbolAddress((void**)&dvh, g_dvh);
    cudaGetSymbolAddress((void**)&qbh, g_qbh);
    cudaGetSymbolAddress((void**)&q2,  g_q2);
    cudaGetSymbolAddress((void**)&wqt, g_wqt);
    cudaGetSymbolAddress((void**)&wkt, g_wkt);
    cudaGetSymbolAddress((void**)&wkq, g_wkq);
    cudaGetSymbolAddress((void**)&wvh, g_wvh);
    cudaGetSymbolAddress((void**)&g1h, g_g1h);
    cudaGetSymbolAddress((void**)&wb,  g_wb);
    cudaGetSymbolAddress((void**)&sp,  g_sumpart);
    cudaGetSymbolAddress((void**)&attnp, g_attnp);
    cudaGetSymbolAddress((void**)&cath, g_cath);
    cudaGetSymbolAddress((void**)&attn, g_attn);
    cudaGetSymbolAddress((void**)&part, g_part);
    cudaGetSymbolAddress((void**)&bias2, g_bias2);

    const float q_alpha = 0.08838834764831845f;   // D^-0.5 / TEMP

    // --- all conversions / transposes / layout prep in one launch ---
    prep_all<<<NB_PALL, 256>>>((const float4*)dk, (__half2*)dkh,
                               (const float4*)dv, (__half2*)dvh,
                               (const float4*)Wv, (__half2*)wvh,
                               (const float4*)Wg1, (__half2*)g1h,
                               Wq, wqt, Wk, wkt, q, prev, qbh, cath);
    bias2_kernel<<<DIM, 256>>>(bq, wkt, bias2, q_alpha);

    // --- Wkq = alpha*(Wk^T · Wq) -> fp16, single-K ---
    gemm_f16<0><<<dim3(4, 4, 1), 256, GSMEM>>>(
        wkt, wqt, nullptr, wkq,
        DIM, DIM, DIM, DIM, nullptr, 0, q_alpha, 0, 1, 0, nullptr);

    // --- q2 = qb @ Wkq^T + bias2 -> fp16, single-K ---
    gemm_f16<0><<<dim3(4, 8, 1), 256, GSMEM>>>(
        qbh, wkq, nullptr, q2,
        DIM, DIM, DIM, DIM, bias2, 1, 1.f, 0, 1, 0, nullptr);

    // --- logits+exp fused: wb = exp(q2 @ dk^T) fp16 + row partial sums ---
    gemm_f16<0><<<dim3(RQ / 128, NKV / 128, 1), 256, GSMEM>>>(
        q2, dkh, nullptr, wb,
        DIM, DIM, NKV, DIM, nullptr, 0, 1.f, 1, 3, 0, sp);

    // --- attn split-K z=32: part[z] = wb @ dv (B in [K,N], trans-ldmatrix) ---
    gemm_f16<1><<<dim3(DIM / 128, RQ / 128, ASPLIT), 256, GSMEM>>>(
        wb, dvh, part, nullptr,
        NKV, DIM, DIM, AKSLICE, nullptr, 0, 1.f, 0, 0, (long long)RQ * DIM, nullptr);

    // --- fused invsum + split-K reduce + normalize -> attnp fp16 ---
    attn_reduce<<<RQ, 256>>>(part, sp, attnp);

    // --- attn = attnp @ Wv^T + bv -> fp32 attn + fp16 cath (dual), single-K ---
    gemm_f16<0><<<dim3(4, 8, 1), 256, GSMEM>>>(
        attnp, wvh, attn, cath,
        DIM, DIM, DIM, DIM, bv, 1, 1.f, 0, 4, (long long)(2 * DIM), nullptr);

    // --- gate GEMM: gg = cat @ Wg1^T -> fp32 direct, single-K (K=1024) ---
    gemm_f16<0><<<dim3(4, 8, 1), 256, GSMEM>>>(
        cath, g1h, part, nullptr,
        2 * DIM, 2 * DIM, DIM, 2 * DIM, nullptr, 0, 1.f, 0, 0, 0, nullptr);

    // --- fused gate(+bg1,relu) + sigma + final blend ---
    gate_sigma_final<<<RQ, 128>>>(part, bg1, Wg2, bg2, attn, prev, out);
}

// round 16
// speedup vs baseline: 1.0692x; 1.0692x over previous
#include <cuda_runtime.h>
#include <cuda_fp16.h>
#include <cstdint>

#define SEQ   256
#define BATCH 4
#define DIM   512
#define NKV   32768
#define RQ    (SEQ * BATCH)          // 1024
#define ASPLIT 32
#define AKSLICE (NKV / ASPLIT)       // 1024
#define GSPLIT 4
#define NSUM  (NKV / 128)            // 256

typedef unsigned int u32;
typedef __half fp16;

// ======================= device scratch ====================================
__device__ __align__(16) fp16 g_dkh[NKV * DIM];            // dk fp16 [NKV,DIM]
__device__ __align__(16) fp16 g_dvh[NKV * DIM];            // dv fp16 [NKV,DIM]
__device__ __align__(16) fp16 g_qbh[RQ * DIM];
__device__ __align__(16) fp16 g_q2 [RQ * DIM];
__device__ __align__(16) fp16 g_wqt[DIM * DIM];            // Wq^T
__device__ __align__(16) fp16 g_wkt[DIM * DIM];            // Wk^T
__device__ __align__(16) fp16 g_wkq[DIM * DIM];            // alpha*Wk^T*Wq
__device__ __align__(16) fp16 g_wvh[DIM * DIM];
__device__ __align__(16) fp16 g_g1h[DIM * 2 * DIM];
__device__ __align__(16) float g_bias2[DIM];
__device__ __align__(16) fp16 g_wb[(size_t)RQ * NKV];      // exp weights fp16
__device__ __align__(16) float g_sumpart[(size_t)RQ * NSUM];
__device__ __align__(16) fp16 g_attnp[RQ * DIM];
__device__ __align__(16) fp16 g_cath[RQ * 2 * DIM];
__device__ __align__(16) float g_attn[RQ * DIM];
__device__ __align__(16) float g_part[(size_t)ASPLIT * RQ * DIM];   // split-K scratch

// ======================= PTX helpers =======================================
__device__ __forceinline__ u32 smem_u32(const void* p) {
    u32 a;
    asm("{ .reg .u64 t; cvta.to.shared.u64 t, %1; cvt.u32.u64 %0, t; }"
        : "=r"(a) : "l"(p));
    return a;
}

#define CP_ASYNC16(dst, src) \
    asm volatile("cp.async.cg.shared.global [%0], [%1], 16;" :: "r"(dst), "l"(src))
#define CP_COMMIT() asm volatile("cp.async.commit_group;" ::: "memory")
#define CP_WAIT(n)  asm volatile("cp.async.wait_group %0;" :: "n"(n) : "memory")

#define LDMX4(r, addr) \
    asm volatile("ldmatrix.sync.aligned.m8n8.x4.shared.b16 {%0,%1,%2,%3}, [%4];" \
        : "=r"((r)[0]), "=r"((r)[1]), "=r"((r)[2]), "=r"((r)[3]) : "r"(addr))

#define LDMX4T(r, addr) \
    asm volatile("ldmatrix.sync.aligned.m8n8.x4.trans.shared.b16 {%0,%1,%2,%3}, [%4];" \
        : "=r"((r)[0]), "=r"((r)[1]), "=r"((r)[2]), "=r"((r)[3]) : "r"(addr))

#define MMA_F16(d, a, b) \
    asm volatile("mma.sync.aligned.m16n8k16.row.col.f32.f16.f16.f32 " \
        "{%0,%1,%2,%3}, {%4,%5,%6,%7}, {%8,%9}, {%0,%1,%2,%3};" \
        : "+f"((d)[0]), "+f"((d)[1]), "+f"((d)[2]), "+f"((d)[3]) \
        : "r"((a)[0]), "r"((a)[1]), "r"((a)[2]), "r"((a)[3]), \
          "r"((b)[0]), "r"((b)[1]))

__device__ __forceinline__ float fast_exp(float x) {
    float t = x * 1.4426950408889634f;
    t = fmaxf(t, -125.0f);
    float fi = floorf(t);
    float f = t - fi;
    float p = 1.5403530393381608e-4f;
    p = fmaf(p, f, 1.3333558146428443e-3f);
    p = fmaf(p, f, 9.618129107628477e-3f);
    p = fmaf(p, f, 5.550410866482158e-2f);
    p = fmaf(p, f, 2.402265069591007e-1f);
    p = fmaf(p, f, 6.931471805599453e-1f);
    p = fmaf(p, f, 1.0f);
    return p * __int_as_float(((int)fi + 127) << 23);
}

__device__ __forceinline__ u32 h2u(__half2 h) { return *(u32*)&h; }

// cvt 2 float4 -> uint4 of 4 half2
__device__ __forceinline__ uint4 cvt8(float4 a, float4 b) {
    uint4 o;
    o.x = h2u(__floats2half2_rn(a.x, a.y));
    o.y = h2u(__floats2half2_rn(a.z, a.w));
    o.z = h2u(__floats2half2_rn(b.x, b.y));
    o.w = h2u(__floats2half2_rn(b.z, b.w));
    return o;
}

// ======================= pipelined HMMA fp16 GEMM ==========================
// C[M,N] = A[M,K] * B^T, fp32 accumulate
// BKN=0: B stored [N,K] row-major; BKN=1: B stored [K,N] row-major
// out_mode: 0 fp32 partials (z*strideZ, alpha+bias applied);
//           1 fp16; 3 exp(acc)->fp16 + per-(row,ntile) partial sums
#define GKC 64
#define SROW 144
#define TILE_B (128 * SROW)        // A tile bytes: 18432
#define GSMEM (3 * (2 * TILE_B))   // 110592

template<int BKN>
__global__ __launch_bounds__(256, 2)
void gemm_f16(const fp16* __restrict__ A, const fp16* __restrict__ B,
              float* __restrict__ Cf, fp16* __restrict__ Ch,
              int lda, int ldb, int ldc, int kslice,
              const float* __restrict__ bias, int bias_mode,
              float alpha, int swap, int out_mode,
              long long strideZ, float* __restrict__ sums)
{
    constexpr int SROWB = BKN ? 272 : SROW;
    constexpr int BT    = BKN ? 64 * 272 : TILE_B;
    constexpr int STG   = TILE_B + BT;

    extern __shared__ char smem[];
    const u32 sb = smem_u32(smem);
    const int tid = threadIdx.x;
    const int lane = tid & 31, wid = tid >> 5;
    const int wm = wid >> 1, wn = wid & 1;
    const int mtile = swap ? blockIdx.x : blockIdx.y;
    const int ntile = swap ? blockIdx.y : blockIdx.x;
    const int z = blockIdx.z;
    const long long kbase = (long long)z * kslice;
    const int NC = kslice / GKC;

    auto load_stage = [&](int c) {
        const u32 st = sb + (u32)(c % 3) * STG;
        const long long kb = kbase + (long long)c * GKC;
#pragma unroll
        for (int i = 0; i < 4; i++) {               // A tile: 128 rows x 128B
            const int idx = tid + i * 256;
            const int row = idx >> 3, ch = idx & 7;
            const u32 so = (u32)(row * SROW + ch * 16);
            const long long aoff = (long long)(mtile * 128 + row) * lda + kb + ch * 8;
            CP_ASYNC16(st + so, (const char*)(A + aoff));
        }
        if (BKN) {
#pragma unroll
            for (int i = 0; i < 4; i++) {           // B tile: 64 K-rows x 256B
                const int idx = tid + i * 256;
                const int row = idx >> 4, ch = idx & 15;
                const u32 so = (u32)(row * SROWB + ch * 16);
                const long long boff = (kb + row) * (long long)ldb
                                     + (long long)ntile * 128 + ch * 8;
                CP_ASYNC16(st + TILE_B + so, (const char*)(B + boff));
            }
        } else {
#pragma unroll
            for (int i = 0; i < 4; i++) {           // B tile: 128 N-rows x 128B
                const int idx = tid + i * 256;
                const int row = idx >> 3, ch = idx & 7;
                const u32 so = (u32)(row * SROWB + ch * 16);
                const long long boff = (long long)(ntile * 128 + row) * ldb + kb + ch * 8;
                CP_ASYNC16(st + TILE_B + so, (const char*)(B + boff));
            }
        }
        CP_COMMIT();
    };

    float acc[2][8][4];
#pragma unroll
    for (int mt = 0; mt < 2; mt++)
#pragma unroll
        for (int nt = 0; nt < 8; nt++)
#pragma unroll
            for (int j = 0; j < 4; j++) acc[mt][nt][j] = 0.f;

    load_stage(0);
    if (NC > 1) load_stage(1);

    const u32 a_row = (u32)(wm * 32 + (lane & 15));
    const u32 a_ke  = (u32)((lane >> 4) * 8);
    const u32 b_row = (u32)(wn * 64 + ((lane >> 4) << 3) + (lane & 7));
    const u32 b_ke  = (u32)(((lane >> 3) & 1) * 8);
    const u32 bt_k  = (u32)(((lane >> 3) & 1) * 8 + (lane & 7));
    const u32 bt_n  = (u32)((lane >> 4) << 3);

    for (int c = 0; c < NC; c++) {
        if (c + 1 < NC) { CP_WAIT(1); } else { CP_WAIT(0); }
        __syncthreads();
        if (c + 2 < NC) load_stage(c + 2);

        const u32 st = sb + (u32)(c % 3) * STG;
#pragma unroll
        for (int ks = 0; ks < 4; ks++) {
            const u32 k0 = ks * 16;
            u32 af[2][4], bfr[8][2];
#pragma unroll
            for (int mt = 0; mt < 2; mt++) {
                const u32 addr = st + (a_row + mt * 16) * SROW + (k0 + a_ke) * 2;
                LDMX4(af[mt], addr);
            }
#pragma unroll
            for (int nt2 = 0; nt2 < 4; nt2++) {
                u32 r[4];
                if (BKN) {
                    const u32 addr = st + TILE_B + (k0 + bt_k) * SROWB
                                   + (u32)(wn * 64 + nt2 * 16 + bt_n) * 2;
                    LDMX4T(r, addr);
                } else {
                    const u32 addr = st + TILE_B + (b_row + nt2 * 16) * SROWB
                                   + (k0 + b_ke) * 2;
                    LDMX4(r, addr);
                }
                bfr[2 * nt2][0] = r[0]; bfr[2 * nt2][1] = r[1];
                bfr[2 * nt2 + 1][0] = r[2]; bfr[2 * nt2 + 1][1] = r[3];
            }
#pragma unroll
            for (int mt = 0; mt < 2; mt++)
#pragma unroll
                for (int nt = 0; nt < 8; nt++)
                    MMA_F16(acc[mt][nt], af[mt], bfr[nt]);
        }
    }
    __syncthreads();

    // ---------------- epilogue ---------------------------------------------
    float* stage = (float*)smem;                    // [128][132]
    const int l4 = lane >> 2, l2 = (lane & 3) * 2;

#pragma unroll
    for (int mt = 0; mt < 2; mt++) {
        const int lr = wm * 32 + mt * 16 + l4;
#pragma unroll
        for (int nt = 0; nt < 8; nt++) {
            const int lc = wn * 64 + nt * 8 + l2;
            float v0, v1, v2, v3;
            if (out_mode == 3) {
                v0 = fast_exp(acc[mt][nt][0]);
                v1 = fast_exp(acc[mt][nt][1]);
                v2 = fast_exp(acc[mt][nt][2]);
                v3 = fast_exp(acc[mt][nt][3]);
            } else {
                float bc0 = 0.f, bc1 = 0.f;
                if (bias_mode == 1) {
                    bc0 = bias[ntile * 128 + lc];
                    bc1 = bias[ntile * 128 + lc + 1];
                }
                v0 = (acc[mt][nt][0] + bc0) * alpha;
                v1 = (acc[mt][nt][1] + bc1) * alpha;
                v2 = (acc[mt][nt][2] + bc0) * alpha;
                v3 = (acc[mt][nt][3] + bc1) * alpha;
            }
            stage[lr * 132 + lc] = v0;
            stage[lr * 132 + lc + 1] = v1;
            stage[(lr + 8) * 132 + lc] = v2;
            stage[(lr + 8) * 132 + lc + 1] = v3;
        }
    }
    __syncthreads();

    if (out_mode == 0) {
        float* Cp = Cf + (long long)z * strideZ
                  + (long long)(mtile * 128) * ldc + ntile * 128;
#pragma unroll
        for (int i = 0; i < 16; i++) {
            const int idx = tid + i * 256;
            const int rr = idx >> 5, c4 = (idx & 31) * 4;
            float4 v = *(float4*)&stage[rr * 132 + c4];
            *(float4*)(Cp + (long long)rr * ldc + c4) = v;
        }
    } else {
        fp16* Hp = Ch + (long long)(mtile * 128) * ldc + ntile * 128;
#pragma unroll
        for (int i = 0; i < 16; i++) {
            const int idx = tid + i * 256;
            const int rr = idx >> 5, c4 = (idx & 31) * 4;
            float4 v = *(float4*)&stage[rr * 132 + c4];
            __half2* hq = (__half2*)(Hp + (long long)rr * ldc + c4);
            hq[0] = __floats2half2_rn(v.x, v.y);
            hq[1] = __floats2half2_rn(v.z, v.w);
        }
        if (out_mode == 3) {
            const int r = tid >> 1, h = tid & 1;
            float s = 0.f;
            const float* rp = &stage[r * 132 + h * 64];
#pragma unroll
            for (int j = 0; j < 64; j++) s += rp[j];
            s += __shfl_xor_sync(0xffffffffu, s, 1);
            if (h == 0)
                sums[(size_t)(mtile * 128 + r) * NSUM + ntile] = s;
        }
    }
}

// ======================= merged prep kernel ================================
// blocks [0,2048): vectorized grid-stride converts (dk, dv, Wv, Wg1)
// blocks [2048,2560): Wq/Wk transpose+convert
// blocks [2560,4608): q/prev layout prep
#define NB_CVT 2048
#define NB_TT  512
#define NB_PREP 2048
#define NB_PALL (NB_CVT + NB_TT + NB_PREP)

__global__ void prep_all(const float4* __restrict__ dk, uint4* __restrict__ dkh,
                         const float4* __restrict__ dv, uint4* __restrict__ dvh,
                         const float4* __restrict__ wv, uint4* __restrict__ wvh,
                         const float4* __restrict__ wg1, uint4* __restrict__ g1h,
                         const float* __restrict__ wq, fp16* __restrict__ wqt,
                         const float* __restrict__ wk, fp16* __restrict__ wkt,
                         const float* __restrict__ q, const float* __restrict__ prev,
                         fp16* __restrict__ qbh, fp16* __restrict__ cath)
{
    __shared__ float tile[32][33];
    const int b = blockIdx.x;
    const int tid = threadIdx.x;

    if (b < NB_CVT) {
        const int N_DK8 = NKV * DIM / 8;         // uint4 units
        const int N_WV8 = DIM * DIM / 8;
        const int N_G18 = DIM * 2 * DIM / 8;
        const int stride = NB_CVT * 256;
        const int t0 = b * 256 + tid;
        for (int i = t0; i < N_DK8; i += stride) {
            dkh[i] = cvt8(dk[2 * i], dk[2 * i + 1]);
            dvh[i] = cvt8(dv[2 * i], dv[2 * i + 1]);
        }
        for (int i = t0; i < N_G18; i += stride) {
            g1h[i] = cvt8(wg1[2 * i], wg1[2 * i + 1]);
            if (i < N_WV8)
                wvh[i] = cvt8(wv[2 * i], wv[2 * i + 1]);
        }
    } else if (b < NB_CVT + NB_TT) {
        const int bb = b - NB_CVT;
        const int bx = bb & 15, by = (bb >> 4) & 15, bz = bb >> 8;
        const float* src = bz ? wk : wq;
        fp16* dst = bz ? wkt : wqt;
        const int c0 = bx * 32, r0 = by * 32;
        const int tx = tid & 31, ty = tid >> 5;     // 32 x 8
#pragma unroll
        for (int i = 0; i < 32; i += 8)
            tile[ty + i][tx] = src[(size_t)(r0 + ty + i) * DIM + c0 + tx];
        __syncthreads();
#pragma unroll
        for (int i = 0; i < 32; i += 8)
            dst[(size_t)(c0 + ty + i) * DIM + r0 + tx] = __float2half(tile[tx][ty + i]);
    } else {
        const int i = (b - NB_CVT - NB_TT) * 256 + tid;
        const int d = i & (DIM - 1);
        const int t = i >> 9;
        const int ba = t & (BATCH - 1);
        const int s = t >> 2;
        const int r = ba * SEQ + s;
        qbh[(size_t)r * DIM + d] = __float2half(q[i]);
        cath[(size_t)r * 2 * DIM + DIM + d] = __float2half(prev[i]);
    }
}

// ======================= merged wkq-reduce + bias2 =========================
__global__ void red_wkq_bias2(const float* __restrict__ part,
                              fp16* __restrict__ wkq,
                              const float* __restrict__ bq,
                              const fp16* __restrict__ wkt,
                              float* __restrict__ bias2, float alpha)
{
    const int b = blockIdx.x;
    const int tid = threadIdx.x;                // 256
    if (b < 1024) {
        const int i = b * 256 + tid;
        float s = 0.f;
#pragma unroll
        for (int z = 0; z < 4; z++) s += part[(long long)z * DIM * DIM + i];
        wkq[i] = __float2half(s);
    } else {
        const int j = b - 1024;                 // 0..511
        const __half2 w = ((const __half2*)(wkt + (size_t)j * DIM))[tid];
        float s = fmaf(bq[2 * tid], __half2float(__low2half(w)),
                       bq[2 * tid + 1] * __half2float(__high2half(w)));
#pragma unroll
        for (int o = 16; o; o >>= 1) s += __shfl_xor_sync(0xffffffffu, s, o);
        __shared__ float red[8];
        if ((tid & 31) == 0) red[tid >> 5] = s;
        __syncthreads();
        if (tid == 0) {
            float ss = 0.f;
#pragma unroll
            for (int w8 = 0; w8 < 8; w8++) ss += red[w8];
            bias2[j] = ss * alpha;
        }
    }
}

__global__ void red16(const float* __restrict__ part, int zc, long long stride,
                      const float* __restrict__ bias, fp16* __restrict__ out, int n)
{
    int i = blockIdx.x * 256 + threadIdx.x;
    if (i >= n) return;
    float s = 0.f;
    for (int z = 0; z < zc; z++) s += part[(long long)z * stride + i];
    if (bias) s += bias[i & (DIM - 1)];
    out[i] = __float2half(s);
}

// fused: per-row invsum + 32-way split-K reduce + normalize -> attnp
__global__ void attn_reduce(const float* __restrict__ part, const float* __restrict__ sp,
                            fp16* __restrict__ attnp)
{
    const int r = blockIdx.x;                   // 0..RQ-1
    const int tid = threadIdx.x;                // 256 (== NSUM)
    __shared__ float red[8];
    __shared__ float invs;

    float s = sp[(size_t)r * NSUM + tid];
#pragma unroll
    for (int o = 16; o; o >>= 1) s += __shfl_xor_sync(0xffffffffu, s, o);
    if ((tid & 31) == 0) red[tid >> 5] = s;
    __syncthreads();
    if (tid == 0) {
        float ss = 0.f;
#pragma unroll
        for (int w = 0; w < 8; w++) ss += red[w];
        invs = 1.0f / ss;
    }
    __syncthreads();
    const float inv = invs;

#pragma unroll
    for (int h = 0; h < 2; h++) {
        const int d = h * 256 + tid;
        const size_t i = (size_t)r * DIM + d;
        float v = 0.f;
#pragma unroll
        for (int z = 0; z < ASPLIT; z++) v += part[(size_t)z * RQ * DIM + i];
        attnp[i] = __float2half(v * inv);
    }
}

__global__ void red_af(const float* __restrict__ part, const float* __restrict__ bv,
                       float* __restrict__ attn, fp16* __restrict__ cath)
{
    int i = blockIdx.x * 256 + threadIdx.x;
    int r = i >> 9, d = i & (DIM - 1);
    float s = 0.f;
#pragma unroll
    for (int z = 0; z < 4; z++) s += part[(size_t)z * RQ * DIM + i];
    s += bv[d];
    attn[i] = s;
    cath[(size_t)r * 2 * DIM + d] = __float2half(s);
}

__global__ void gate_sigma_final(const float* __restrict__ partg, const float* __restrict__ bg1,
                                 const float* __restrict__ Wg2, const float* __restrict__ bg2,
                                 const float* __restrict__ attn, const float* __restrict__ prev,
                                 float* __restrict__ out)
{
    const int r = blockIdx.x;
    const int tid = threadIdx.x;                // 128
    float s = 0.f;
    for (int d = tid; d < DIM; d += 128) {
        float v = 0.f;
#pragma unroll
        for (int z = 0; z < GSPLIT; z++)
            v += partg[(size_t)z * RQ * DIM + (size_t)r * DIM + d];
        v = fmaxf(v + bg1[d], 0.f);
        s = fmaf(v, Wg2[d], s);
    }
#pragma unroll
    for (int o = 16; o; o >>= 1) s += __shfl_xor_sync(0xffffffffu, s, o);
    __shared__ float red[4];
    __shared__ float gsh;
    if ((tid & 31) == 0) red[tid >> 5] = s;
    __syncthreads();
    if (tid == 0) {
        float t = red[0] + red[1] + red[2] + red[3] + bg2[0];
        gsh = 1.0f / (1.0f + __expf(-t));
    }
    __syncthreads();
    const float g = gsh;
    const int b = r / SEQ, sq = r % SEQ;
    for (int d = tid; d < DIM; d += 128) {
        const int oi = (sq * BATCH + b) * DIM + d;
        float a = attn[(size_t)r * DIM + d];
        float p = prev[oi];
        out[oi] = fmaf(a - p, g, p);
    }
}

// ======================= launch =============================================
extern "C" void kernel_launch(void* const* d_in, const int* in_sizes, int n_in,
                              void* d_out, int out_size)
{
    (void)in_sizes; (void)n_in; (void)out_size;
    const float* q    = (const float*)d_in[0];
    const float* prev = (const float*)d_in[1];
    const float* Wq   = (const float*)d_in[2];
    const float* bq   = (const float*)d_in[3];
    const float* Wk   = (const float*)d_in[4];
    const float* bk   = (const float*)d_in[5];   (void)bk;  // cancels in softmax
    const float* Wv   = (const float*)d_in[6];
    const float* bv   = (const float*)d_in[7];
    const float* Wg1  = (const float*)d_in[8];
    const float* bg1  = (const float*)d_in[9];
    const float* Wg2  = (const float*)d_in[10];
    const float* bg2  = (const float*)d_in[11];
    const float* dk   = (const float*)d_in[12];
    const float* dv   = (const float*)d_in[13];
    float* out = (float*)d_out;

    cudaFuncSetAttribute(gemm_f16<0>, cudaFuncAttributeMaxDynamicSharedMemorySize, GSMEM);
    cudaFuncSetAttribute(gemm_f16<1>, cudaFuncAttributeMaxDynamicSharedMemorySize, GSMEM);

    fp16 *dkh, *dvh, *qbh, *q2, *wqt, *wkt, *wkq, *wvh, *g1h, *wb, *attnp, *cath;
    float *attn, *part, *sp, *bias2;
    cudaGetSymbolAddress((void**)&dkh, g_dkh);
    cudaGetSymbolAddress((void**)&dvh, g_dvh);
    cudaGetSymbolAddress((void**)&qbh, g_qbh);
    cudaGetSymbolAddress((void**)&q2,  g_q2);
    cudaGetSymbolAddress((void**)&wqt, g_wqt);
    cudaGetSymbolAddress((void**)&wkt, g_wkt);
    cudaGetSymbolAddress((void**)&wkq, g_wkq);
    cudaGetSymbolAddress((void**)&wvh, g_wvh);
    cudaGetSymbolAddress((void**)&g1h, g_g1h);
    cudaGetSymbolAddress((void**)&wb,  g_wb);
    cudaGetSymbolAddress((void**)&sp,  g_sumpart);
    cudaGetSymbolAddress((void**)&attnp, g_attnp);
    cudaGetSymbolAddress((void**)&cath, g_cath);
    cudaGetSymbolAddress((void**)&attn, g_attn);
    cudaGetSymbolAddress((void**)&part, g_part);
    cudaGetSymbolAddress((void**)&bias2, g_bias2);

    const float q_alpha = 0.08838834764831845f;   // D^-0.5 / TEMP

    // --- all conversions / transposes / layout prep in one launch ---
    prep_all<<<NB_PALL, 256>>>((const float4*)dk, (uint4*)dkh,
                               (const float4*)dv, (uint4*)dvh,
                               (const float4*)Wv, (uint4*)wvh,
                               (const float4*)Wg1, (uint4*)g1h,
                               Wq, wqt, Wk, wkt, q, prev, qbh, cath);

    // --- Wkq = alpha*(Wk^T · Wq), split-K z=4 ---
    gemm_f16<0><<<dim3(4, 4, 4), 256, GSMEM>>>(
        wkt, wqt, part, nullptr,
        DIM, DIM, DIM, 128, nullptr, 0, q_alpha, 0, 0, (long long)DIM * DIM, nullptr);
    // --- merged: wkq reduce + bias2 ---
    red_wkq_bias2<<<1536, 256>>>(part, wkq, bq, wkt, bias2, q_alpha);

    // --- q2 = qb @ Wkq^T + bias2, split-K z=4 ---
    gemm_f16<0><<<dim3(4, 8, 4), 256, GSMEM>>>(
        qbh, wkq, part, nullptr,
        DIM, DIM, DIM, 128, nullptr, 0, 1.f, 0, 0, (long long)RQ * DIM, nullptr);
    red16<<<(RQ * DIM) / 256, 256>>>(part, 4, (long long)RQ * DIM, bias2, q2, RQ * DIM);

    // --- logits+exp fused: wb = exp(q2 @ dk^T) fp16 + row partial sums ---
    gemm_f16<0><<<dim3(RQ / 128, NKV / 128, 1), 256, GSMEM>>>(
        q2, dkh, nullptr, wb,
        DIM, DIM, NKV, DIM, nullptr, 0, 1.f, 1, 3, 0, sp);

    // --- attn split-K z=32: part[z] = wb @ dv (B in [K,N], trans-ldmatrix) ---
    gemm_f16<1><<<dim3(DIM / 128, RQ / 128, ASPLIT), 256, GSMEM>>>(
        wb, dvh, part, nullptr,
        NKV, DIM, DIM, AKSLICE, nullptr, 0, 1.f, 0, 0, (long long)RQ * DIM, nullptr);

    // --- fused invsum + split-K reduce + normalize -> attnp fp16 ---
    attn_reduce<<<RQ, 256>>>(part, sp, attnp);

    // --- attn = attnp @ Wv^T + bv, split-K z=4 ---
    gemm_f16<0><<<dim3(4, 8, 4), 256, GSMEM>>>(
        attnp, wvh, part, nullptr,
        DIM, DIM, DIM, 128, nullptr, 0, 1.f, 0, 0, (long long)RQ * DIM, nullptr);
    red_af<<<(RQ * DIM) / 256, 256>>>(part, bv, attn, cath);

    // --- gate GEMM: part[z] = cat @ Wg1^T slices, z=4 (K=1024) ---
    gemm_f16<0><<<dim3(4, 8, GSPLIT), 256, GSMEM>>>(
        cath, g1h, part, nullptr,
        2 * DIM, 2 * DIM, DIM, 256, nullptr, 0, 1.f, 0, 0, (long long)RQ * DIM, nullptr);

    // --- fused gate-reduce + relu + sigma + final blend ---
    gate_sigma_final<<<RQ, 128>>>(part, bg1, Wg2, bg2, attn, prev, out);
}

// round 17
// speedup vs baseline: 1.0975x; 1.0265x over previous
#include <cuda_runtime.h>
#include <cuda_fp16.h>
#include <cstdint>

#define SEQ   256
#define BATCH 4
#define DIM   512
#define NKV   32768
#define RQ    (SEQ * BATCH)          // 1024
#define ASPLIT 32
#define AKSLICE (NKV / ASPLIT)       // 1024
#define GSPLIT 4
#define NSUM  (NKV / 128)            // 256

typedef unsigned int u32;
typedef __half fp16;

// ======================= device scratch ====================================
__device__ __align__(16) fp16 g_dkh[NKV * DIM];            // dk fp16 [NKV,DIM]
__device__ __align__(16) fp16 g_dvh[NKV * DIM];            // dv fp16 [NKV,DIM]
__device__ __align__(16) fp16 g_qbh[RQ * DIM];
__device__ __align__(16) fp16 g_q2 [RQ * DIM];
__device__ __align__(16) fp16 g_wqt[DIM * DIM];            // Wq^T
__device__ __align__(16) fp16 g_wkt[DIM * DIM];            // Wk^T
__device__ __align__(16) fp16 g_wkq[DIM * DIM];            // alpha*Wk^T*Wq
__device__ __align__(16) fp16 g_wvh[DIM * DIM];
__device__ __align__(16) fp16 g_g1h[DIM * 2 * DIM];
__device__ __align__(16) float g_bias2[DIM];
__device__ __align__(16) fp16 g_wb[(size_t)RQ * NKV];      // exp weights fp16
__device__ __align__(16) float g_sumpart[(size_t)RQ * NSUM];
__device__ __align__(16) fp16 g_attnp[RQ * DIM];
__device__ __align__(16) fp16 g_cath[RQ * 2 * DIM];
__device__ __align__(16) float g_attn[RQ * DIM];
__device__ __align__(16) float g_part[(size_t)4 * RQ * DIM];        // fp32 split-K scratch
__device__ __align__(16) fp16 g_parth[(size_t)ASPLIT * RQ * DIM];   // fp16 split-K scratch

// ======================= PTX helpers =======================================
__device__ __forceinline__ u32 smem_u32(const void* p) {
    u32 a;
    asm("{ .reg .u64 t; cvta.to.shared.u64 t, %1; cvt.u32.u64 %0, t; }"
        : "=r"(a) : "l"(p));
    return a;
}

#define CP_ASYNC16(dst, src) \
    asm volatile("cp.async.cg.shared.global [%0], [%1], 16;" :: "r"(dst), "l"(src))
#define CP_COMMIT() asm volatile("cp.async.commit_group;" ::: "memory")
#define CP_WAIT(n)  asm volatile("cp.async.wait_group %0;" :: "n"(n) : "memory")

#define LDMX4(r, addr) \
    asm volatile("ldmatrix.sync.aligned.m8n8.x4.shared.b16 {%0,%1,%2,%3}, [%4];" \
        : "=r"((r)[0]), "=r"((r)[1]), "=r"((r)[2]), "=r"((r)[3]) : "r"(addr))

#define LDMX4T(r, addr) \
    asm volatile("ldmatrix.sync.aligned.m8n8.x4.trans.shared.b16 {%0,%1,%2,%3}, [%4];" \
        : "=r"((r)[0]), "=r"((r)[1]), "=r"((r)[2]), "=r"((r)[3]) : "r"(addr))

#define MMA_F16(d, a, b) \
    asm volatile("mma.sync.aligned.m16n8k16.row.col.f32.f16.f16.f32 " \
        "{%0,%1,%2,%3}, {%4,%5,%6,%7}, {%8,%9}, {%0,%1,%2,%3};" \
        : "+f"((d)[0]), "+f"((d)[1]), "+f"((d)[2]), "+f"((d)[3]) \
        : "r"((a)[0]), "r"((a)[1]), "r"((a)[2]), "r"((a)[3]), \
          "r"((b)[0]), "r"((b)[1]))

__device__ __forceinline__ float fast_exp(float x) {
    float t = x * 1.4426950408889634f;
    t = fmaxf(t, -125.0f);
    float fi = floorf(t);
    float f = t - fi;
    float p = 1.5403530393381608e-4f;
    p = fmaf(p, f, 1.3333558146428443e-3f);
    p = fmaf(p, f, 9.618129107628477e-3f);
    p = fmaf(p, f, 5.550410866482158e-2f);
    p = fmaf(p, f, 2.402265069591007e-1f);
    p = fmaf(p, f, 6.931471805599453e-1f);
    p = fmaf(p, f, 1.0f);
    return p * __int_as_float(((int)fi + 127) << 23);
}

__device__ __forceinline__ u32 h2u(__half2 h) { return *(u32*)&h; }

__device__ __forceinline__ uint4 cvt8(float4 a, float4 b) {
    uint4 o;
    o.x = h2u(__floats2half2_rn(a.x, a.y));
    o.y = h2u(__floats2half2_rn(a.z, a.w));
    o.z = h2u(__floats2half2_rn(b.x, b.y));
    o.w = h2u(__floats2half2_rn(b.z, b.w));
    return o;
}

// ======================= pipelined HMMA fp16 GEMM ==========================
// C[M,N] = A[M,K] * B^T, fp32 accumulate
// BKN=0: B stored [N,K] row-major; BKN=1: B stored [K,N] row-major
// out_mode: 0 fp32 partials (z*strideZ, alpha+bias applied);
//           1 fp16; 3 exp(acc)->fp16 + per-(row,ntile) partial sums;
//           5 fp16 partials (z*strideZ)
#define GKC 64
#define SROW 144
#define TILE_B (128 * SROW)        // A tile bytes: 18432
#define GSMEM (3 * (2 * TILE_B))   // 110592

template<int BKN>
__global__ __launch_bounds__(256, 2)
void gemm_f16(const fp16* __restrict__ A, const fp16* __restrict__ B,
              float* __restrict__ Cf, fp16* __restrict__ Ch,
              int lda, int ldb, int ldc, int kslice,
              const float* __restrict__ bias, int bias_mode,
              float alpha, int swap, int out_mode,
              long long strideZ, float* __restrict__ sums)
{
    constexpr int SROWB = BKN ? 272 : SROW;
    constexpr int BT    = BKN ? 64 * 272 : TILE_B;
    constexpr int STG   = TILE_B + BT;

    extern __shared__ char smem[];
    const u32 sb = smem_u32(smem);
    const int tid = threadIdx.x;
    const int lane = tid & 31, wid = tid >> 5;
    const int wm = wid >> 1, wn = wid & 1;
    const int mtile = swap ? blockIdx.x : blockIdx.y;
    const int ntile = swap ? blockIdx.y : blockIdx.x;
    const int z = blockIdx.z;
    const long long kbase = (long long)z * kslice;
    const int NC = kslice / GKC;

    auto load_stage = [&](int c) {
        const u32 st = sb + (u32)(c % 3) * STG;
        const long long kb = kbase + (long long)c * GKC;
#pragma unroll
        for (int i = 0; i < 4; i++) {               // A tile: 128 rows x 128B
            const int idx = tid + i * 256;
            const int row = idx >> 3, ch = idx & 7;
            const u32 so = (u32)(row * SROW + ch * 16);
            const long long aoff = (long long)(mtile * 128 + row) * lda + kb + ch * 8;
            CP_ASYNC16(st + so, (const char*)(A + aoff));
        }
        if (BKN) {
#pragma unroll
            for (int i = 0; i < 4; i++) {           // B tile: 64 K-rows x 256B
                const int idx = tid + i * 256;
                const int row = idx >> 4, ch = idx & 15;
                const u32 so = (u32)(row * SROWB + ch * 16);
                const long long boff = (kb + row) * (long long)ldb
                                     + (long long)ntile * 128 + ch * 8;
                CP_ASYNC16(st + TILE_B + so, (const char*)(B + boff));
            }
        } else {
#pragma unroll
            for (int i = 0; i < 4; i++) {           // B tile: 128 N-rows x 128B
                const int idx = tid + i * 256;
                const int row = idx >> 3, ch = idx & 7;
                const u32 so = (u32)(row * SROWB + ch * 16);
                const long long boff = (long long)(ntile * 128 + row) * ldb + kb + ch * 8;
                CP_ASYNC16(st + TILE_B + so, (const char*)(B + boff));
            }
        }
        CP_COMMIT();
    };

    float acc[2][8][4];
#pragma unroll
    for (int mt = 0; mt < 2; mt++)
#pragma unroll
        for (int nt = 0; nt < 8; nt++)
#pragma unroll
            for (int j = 0; j < 4; j++) acc[mt][nt][j] = 0.f;

    load_stage(0);
    if (NC > 1) load_stage(1);

    const u32 a_row = (u32)(wm * 32 + (lane & 15));
    const u32 a_ke  = (u32)((lane >> 4) * 8);
    const u32 b_row = (u32)(wn * 64 + ((lane >> 4) << 3) + (lane & 7));
    const u32 b_ke  = (u32)(((lane >> 3) & 1) * 8);
    const u32 bt_k  = (u32)(((lane >> 3) & 1) * 8 + (lane & 7));
    const u32 bt_n  = (u32)((lane >> 4) << 3);

    for (int c = 0; c < NC; c++) {
        if (c + 1 < NC) { CP_WAIT(1); } else { CP_WAIT(0); }
        __syncthreads();
        if (c + 2 < NC) load_stage(c + 2);

        const u32 st = sb + (u32)(c % 3) * STG;
#pragma unroll
        for (int ks = 0; ks < 4; ks++) {
            const u32 k0 = ks * 16;
            u32 af[2][4], bfr[8][2];
#pragma unroll
            for (int mt = 0; mt < 2; mt++) {
                const u32 addr = st + (a_row + mt * 16) * SROW + (k0 + a_ke) * 2;
                LDMX4(af[mt], addr);
            }
#pragma unroll
            for (int nt2 = 0; nt2 < 4; nt2++) {
                u32 r[4];
                if (BKN) {
                    const u32 addr = st + TILE_B + (k0 + bt_k) * SROWB
                                   + (u32)(wn * 64 + nt2 * 16 + bt_n) * 2;
                    LDMX4T(r, addr);
                } else {
                    const u32 addr = st + TILE_B + (b_row + nt2 * 16) * SROWB
                                   + (k0 + b_ke) * 2;
                    LDMX4(r, addr);
                }
                bfr[2 * nt2][0] = r[0]; bfr[2 * nt2][1] = r[1];
                bfr[2 * nt2 + 1][0] = r[2]; bfr[2 * nt2 + 1][1] = r[3];
            }
#pragma unroll
            for (int mt = 0; mt < 2; mt++)
#pragma unroll
                for (int nt = 0; nt < 8; nt++)
                    MMA_F16(acc[mt][nt], af[mt], bfr[nt]);
        }
    }
    __syncthreads();

    // ---------------- epilogue ---------------------------------------------
    float* stage = (float*)smem;                    // [128][132]
    const int l4 = lane >> 2, l2 = (lane & 3) * 2;

#pragma unroll
    for (int mt = 0; mt < 2; mt++) {
        const int lr = wm * 32 + mt * 16 + l4;
#pragma unroll
        for (int nt = 0; nt < 8; nt++) {
            const int lc = wn * 64 + nt * 8 + l2;
            float v0, v1, v2, v3;
            if (out_mode == 3) {
                v0 = fast_exp(acc[mt][nt][0]);
                v1 = fast_exp(acc[mt][nt][1]);
                v2 = fast_exp(acc[mt][nt][2]);
                v3 = fast_exp(acc[mt][nt][3]);
            } else {
                float bc0 = 0.f, bc1 = 0.f;
                if (bias_mode == 1) {
                    bc0 = bias[ntile * 128 + lc];
                    bc1 = bias[ntile * 128 + lc + 1];
                }
                v0 = (acc[mt][nt][0] + bc0) * alpha;
                v1 = (acc[mt][nt][1] + bc1) * alpha;
                v2 = (acc[mt][nt][2] + bc0) * alpha;
                v3 = (acc[mt][nt][3] + bc1) * alpha;
            }
            stage[lr * 132 + lc] = v0;
            stage[lr * 132 + lc + 1] = v1;
            stage[(lr + 8) * 132 + lc] = v2;
            stage[(lr + 8) * 132 + lc + 1] = v3;
        }
    }
    __syncthreads();

    if (out_mode == 0) {
        float* Cp = Cf + (long long)z * strideZ
                  + (long long)(mtile * 128) * ldc + ntile * 128;
#pragma unroll
        for (int i = 0; i < 16; i++) {
            const int idx = tid + i * 256;
            const int rr = idx >> 5, c4 = (idx & 31) * 4;
            float4 v = *(float4*)&stage[rr * 132 + c4];
            *(float4*)(Cp + (long long)rr * ldc + c4) = v;
        }
    } else {
        fp16* Hp = Ch + (out_mode == 5 ? (long long)z * strideZ : 0ll)
                 + (long long)(mtile * 128) * ldc + ntile * 128;
#pragma unroll
        for (int i = 0; i < 16; i++) {
            const int idx = tid + i * 256;
            const int rr = idx >> 5, c4 = (idx & 31) * 4;
            float4 v = *(float4*)&stage[rr * 132 + c4];
            __half2* hq = (__half2*)(Hp + (long long)rr * ldc + c4);
            hq[0] = __floats2half2_rn(v.x, v.y);
            hq[1] = __floats2half2_rn(v.z, v.w);
        }
        if (out_mode == 3) {
            const int r = tid >> 1, h = tid & 1;
            float s = 0.f;
            const float* rp = &stage[r * 132 + h * 64];
#pragma unroll
            for (int j = 0; j < 64; j++) s += rp[j];
            s += __shfl_xor_sync(0xffffffffu, s, 1);
            if (h == 0)
                sums[(size_t)(mtile * 128 + r) * NSUM + ntile] = s;
        }
    }
}

// ======================= merged prep kernel ================================
#define NB_CVT 2048
#define NB_TT  512
#define NB_PREP 2048
#define NB_PALL (NB_CVT + NB_TT + NB_PREP)

__global__ void prep_all(const float4* __restrict__ dk, uint4* __restrict__ dkh,
                         const float4* __restrict__ dv, uint4* __restrict__ dvh,
                         const float4* __restrict__ wv, uint4* __restrict__ wvh,
                         const float4* __restrict__ wg1, uint4* __restrict__ g1h,
                         const float* __restrict__ wq, fp16* __restrict__ wqt,
                         const float* __restrict__ wk, fp16* __restrict__ wkt,
                         const float* __restrict__ q, const float* __restrict__ prev,
                         fp16* __restrict__ qbh, fp16* __restrict__ cath)
{
    __shared__ float tile[32][33];
    const int b = blockIdx.x;
    const int tid = threadIdx.x;

    if (b < NB_CVT) {
        const int N_DK8 = NKV * DIM / 8;
        const int N_WV8 = DIM * DIM / 8;
        const int N_G18 = DIM * 2 * DIM / 8;
        const int stride = NB_CVT * 256;
        const int t0 = b * 256 + tid;
        for (int i = t0; i < N_DK8; i += stride) {
            dkh[i] = cvt8(dk[2 * i], dk[2 * i + 1]);
            dvh[i] = cvt8(dv[2 * i], dv[2 * i + 1]);
        }
        for (int i = t0; i < N_G18; i += stride) {
            g1h[i] = cvt8(wg1[2 * i], wg1[2 * i + 1]);
            if (i < N_WV8)
                wvh[i] = cvt8(wv[2 * i], wv[2 * i + 1]);
        }
    } else if (b < NB_CVT + NB_TT) {
        const int bb = b - NB_CVT;
        const int bx = bb & 15, by = (bb >> 4) & 15, bz = bb >> 8;
        const float* src = bz ? wk : wq;
        fp16* dst = bz ? wkt : wqt;
        const int c0 = bx * 32, r0 = by * 32;
        const int tx = tid & 31, ty = tid >> 5;
#pragma unroll
        for (int i = 0; i < 32; i += 8)
            tile[ty + i][tx] = src[(size_t)(r0 + ty + i) * DIM + c0 + tx];
        __syncthreads();
#pragma unroll
        for (int i = 0; i < 32; i += 8)
            dst[(size_t)(c0 + ty + i) * DIM + r0 + tx] = __float2half(tile[tx][ty + i]);
    } else {
        const int i = (b - NB_CVT - NB_TT) * 256 + tid;
        const int d = i & (DIM - 1);
        const int t = i >> 9;
        const int ba = t & (BATCH - 1);
        const int s = t >> 2;
        const int r = ba * SEQ + s;
        qbh[(size_t)r * DIM + d] = __float2half(q[i]);
        cath[(size_t)r * 2 * DIM + DIM + d] = __float2half(prev[i]);
    }
}

// ======================= merged wkq-reduce + bias2 =========================
__global__ void red_wkq_bias2(const float* __restrict__ part,
                              fp16* __restrict__ wkq,
                              const float* __restrict__ bq,
                              const fp16* __restrict__ wkt,
                              float* __restrict__ bias2, float alpha)
{
    const int b = blockIdx.x;
    const int tid = threadIdx.x;                // 256
    if (b < 1024) {
        const int i = b * 256 + tid;
        float s = 0.f;
#pragma unroll
        for (int z = 0; z < 4; z++) s += part[(long long)z * DIM * DIM + i];
        wkq[i] = __float2half(s);
    } else {
        const int j = b - 1024;
        const __half2 w = ((const __half2*)(wkt + (size_t)j * DIM))[tid];
        float s = fmaf(bq[2 * tid], __half2float(__low2half(w)),
                       bq[2 * tid + 1] * __half2float(__high2half(w)));
#pragma unroll
        for (int o = 16; o; o >>= 1) s += __shfl_xor_sync(0xffffffffu, s, o);
        __shared__ float red[8];
        if ((tid & 31) == 0) red[tid >> 5] = s;
        __syncthreads();
        if (tid == 0) {
            float ss = 0.f;
#pragma unroll
            for (int w8 = 0; w8 < 8; w8++) ss += red[w8];
            bias2[j] = ss * alpha;
        }
    }
}

__global__ void red16(const float* __restrict__ part, int zc, long long stride,
                      const float* __restrict__ bias, fp16* __restrict__ out, int n)
{
    int i = blockIdx.x * 256 + threadIdx.x;
    if (i >= n) return;
    float s = 0.f;
    for (int z = 0; z < zc; z++) s += part[(long long)z * stride + i];
    if (bias) s += bias[i & (DIM - 1)];
    out[i] = __float2half(s);
}

// fused: per-row invsum + 32-way fp16 split-K reduce + normalize -> attnp
__global__ void attn_reduce(const fp16* __restrict__ ph, const float* __restrict__ sp,
                            fp16* __restrict__ attnp)
{
    const int r = blockIdx.x;                   // 0..RQ-1
    const int tid = threadIdx.x;                // 256 (== NSUM)
    __shared__ float red[8];
    __shared__ float invs;

    float s = sp[(size_t)r * NSUM + tid];
#pragma unroll
    for (int o = 16; o; o >>= 1) s += __shfl_xor_sync(0xffffffffu, s, o);
    if ((tid & 31) == 0) red[tid >> 5] = s;
    __syncthreads();
    if (tid == 0) {
        float ss = 0.f;
#pragma unroll
        for (int w = 0; w < 8; w++) ss += red[w];
        invs = 1.0f / ss;
    }
    __syncthreads();
    const float inv = invs;

    // each thread: one half2 (two d's) per row half
    const int d2 = tid;                          // 0..255 -> covers 512 d's as half2
    const size_t base2 = ((size_t)r * DIM) >> 1;
    float v0 = 0.f, v1 = 0.f;
#pragma unroll
    for (int z = 0; z < ASPLIT; z++) {
        __half2 h = ((const __half2*)ph)[(size_t)z * RQ * DIM / 2 + base2 + d2];
        v0 += __half2float(__low2half(h));
        v1 += __half2float(__high2half(h));
    }
    ((__half2*)attnp)[base2 + d2] = __floats2half2_rn(v0 * inv, v1 * inv);
}

__global__ void red_af(const float* __restrict__ part, const float* __restrict__ bv,
                       float* __restrict__ attn, fp16* __restrict__ cath)
{
    int i = blockIdx.x * 256 + threadIdx.x;
    int r = i >> 9, d = i & (DIM - 1);
    float s = 0.f;
#pragma unroll
    for (int z = 0; z < 4; z++) s += part[(size_t)z * RQ * DIM + i];
    s += bv[d];
    attn[i] = s;
    cath[(size_t)r * 2 * DIM + d] = __float2half(s);
}

__global__ void gate_sigma_final(const fp16* __restrict__ ph, const float* __restrict__ bg1,
                                 const float* __restrict__ Wg2, const float* __restrict__ bg2,
                                 const float* __restrict__ attn, const float* __restrict__ prev,
                                 float* __restrict__ out)
{
    const int r = blockIdx.x;
    const int tid = threadIdx.x;                // 128
    float s = 0.f;
    for (int d = tid; d < DIM; d += 128) {
        float v = 0.f;
#pragma unroll
        for (int z = 0; z < GSPLIT; z++)
            v += __half2float(ph[(size_t)z * RQ * DIM + (size_t)r * DIM + d]);
        v = fmaxf(v + bg1[d], 0.f);
        s = fmaf(v, Wg2[d], s);
    }
#pragma unroll
    for (int o = 16; o; o >>= 1) s += __shfl_xor_sync(0xffffffffu, s, o);
    __shared__ float red[4];
    __shared__ float gsh;
    if ((tid & 31) == 0) red[tid >> 5] = s;
    __syncthreads();
    if (tid == 0) {
        float t = red[0] + red[1] + red[2] + red[3] + bg2[0];
        gsh = 1.0f / (1.0f + __expf(-t));
    }
    __syncthreads();
    const float g = gsh;
    const int b = r / SEQ, sq = r % SEQ;
    for (int d = tid; d < DIM; d += 128) {
        const int oi = (sq * BATCH + b) * DIM + d;
        float a = attn[(size_t)r * DIM + d];
        float p = prev[oi];
        out[oi] = fmaf(a - p, g, p);
    }
}

// ======================= launch =============================================
extern "C" void kernel_launch(void* const* d_in, const int* in_sizes, int n_in,
                              void* d_out, int out_size)
{
    (void)in_sizes; (void)n_in; (void)out_size;
    const float* q    = (const float*)d_in[0];
    const float* prev = (const float*)d_in[1];
    const float* Wq   = (const float*)d_in[2];
    const float* bq   = (const float*)d_in[3];
    const float* Wk   = (const float*)d_in[4];
    const float* bk   = (const float*)d_in[5];   (void)bk;  // cancels in softmax
    const float* Wv   = (const float*)d_in[6];
    const float* bv   = (const float*)d_in[7];
    const float* Wg1  = (const float*)d_in[8];
    const float* bg1  = (const float*)d_in[9];
    const float* Wg2  = (const float*)d_in[10];
    const float* bg2  = (const float*)d_in[11];
    const float* dk   = (const float*)d_in[12];
    const float* dv   = (const float*)d_in[13];
    float* out = (float*)d_out;

    cudaFuncSetAttribute(gemm_f16<0>, cudaFuncAttributeMaxDynamicSharedMemorySize, GSMEM);
    cudaFuncSetAttribute(gemm_f16<1>, cudaFuncAttributeMaxDynamicSharedMemorySize, GSMEM);

    fp16 *dkh, *dvh, *qbh, *q2, *wqt, *wkt, *wkq, *wvh, *g1h, *wb, *attnp, *cath, *parth;
    float *attn, *part, *sp, *bias2;
    cudaGetSymbolAddress((void**)&dkh, g_dkh);
    cudaGetSymbolAddress((void**)&dvh, g_dvh);
    cudaGetSymbolAddress((void**)&qbh, g_qbh);
    cudaGetSymbolAddress((void**)&q2,  g_q2);
    cudaGetSymbolAddress((void**)&wqt, g_wqt);
    cudaGetSymbolAddress((void**)&wkt, g_wkt);
    cudaGetSymbolAddress((void**)&wkq, g_wkq);
    cudaGetSymbolAddress((void**)&wvh, g_wvh);
    cudaGetSymbolAddress((void**)&g1h, g_g1h);
    cudaGetSymbolAddress((void**)&wb,  g_wb);
    cudaGetSymbolAddress((void**)&sp,  g_sumpart);
    cudaGetSymbolAddress((void**)&attnp, g_attnp);
    cudaGetSymbolAddress((void**)&cath, g_cath);
    cudaGetSymbolAddress((void**)&attn, g_attn);
    cudaGetSymbolAddress((void**)&part, g_part);
    cudaGetSymbolAddress((void**)&parth, g_parth);
    cudaGetSymbolAddress((void**)&bias2, g_bias2);

    const float q_alpha = 0.08838834764831845f;   // D^-0.5 / TEMP

    // --- all conversions / transposes / layout prep in one launch ---
    prep_all<<<NB_PALL, 256>>>((const float4*)dk, (uint4*)dkh,
                               (const float4*)dv, (uint4*)dvh,
                               (const float4*)Wv, (uint4*)wvh,
                               (const float4*)Wg1, (uint4*)g1h,
                               Wq, wqt, Wk, wkt, q, prev, qbh, cath);

    // --- Wkq = alpha*(Wk^T · Wq), split-K z=4 ---
    gemm_f16<0><<<dim3(4, 4, 4), 256, GSMEM>>>(
        wkt, wqt, part, nullptr,
        DIM, DIM, DIM, 128, nullptr, 0, q_alpha, 0, 0, (long long)DIM * DIM, nullptr);
    red_wkq_bias2<<<1536, 256>>>(part, wkq, bq, wkt, bias2, q_alpha);

    // --- q2 = qb @ Wkq^T + bias2, split-K z=4 ---
    gemm_f16<0><<<dim3(4, 8, 4), 256, GSMEM>>>(
        qbh, wkq, part, nullptr,
        DIM, DIM, DIM, 128, nullptr, 0, 1.f, 0, 0, (long long)RQ * DIM, nullptr);
    red16<<<(RQ * DIM) / 256, 256>>>(part, 4, (long long)RQ * DIM, bias2, q2, RQ * DIM);

    // --- logits+exp fused: wb = exp(q2 @ dk^T) fp16 + row partial sums ---
    gemm_f16<0><<<dim3(RQ / 128, NKV / 128, 1), 256, GSMEM>>>(
        q2, dkh, nullptr, wb,
        DIM, DIM, NKV, DIM, nullptr, 0, 1.f, 1, 3, 0, sp);

    // --- attn split-K z=32 -> fp16 partials (out_mode 5) ---
    gemm_f16<1><<<dim3(DIM / 128, RQ / 128, ASPLIT), 256, GSMEM>>>(
        wb, dvh, nullptr, parth,
        NKV, DIM, DIM, AKSLICE, nullptr, 0, 1.f, 0, 5, (long long)RQ * DIM, nullptr);

    // --- fused invsum + fp16 split-K reduce + normalize -> attnp fp16 ---
    attn_reduce<<<RQ, 256>>>(parth, sp, attnp);

    // --- attn = attnp @ Wv^T + bv, split-K z=4 (fp32 partials) ---
    gemm_f16<0><<<dim3(4, 8, 4), 256, GSMEM>>>(
        attnp, wvh, part, nullptr,
        DIM, DIM, DIM, 128, nullptr, 0, 1.f, 0, 0, (long long)RQ * DIM, nullptr);
    red_af<<<(RQ * DIM) / 256, 256>>>(part, bv, attn, cath);

    // --- gate GEMM: fp16 partials z=4 (K=1024) ---
    gemm_f16<0><<<dim3(4, 8, GSPLIT), 256, GSMEM>>>(
        cath, g1h, nullptr, parth,
        2 * DIM, 2 * DIM, DIM, 256, nullptr, 0, 1.f, 0, 5, (long long)RQ * DIM, nullptr);

    // --- fused gate-reduce + relu + sigma + final blend ---
    gate_sigma_final<<<RQ, 128>>>(parth, bg1, Wg2, bg2, attn, prev, out);
}